// round 5
// baseline (speedup 1.0000x reference)
#include <cuda_runtime.h>
#include <cuda_bf16.h>
#include <cstdint>

// Problem constants.
#define D    96      // D_IN == D_OUT
#define K2   192     // concat K = 2*D
#define MAXN 50000
#define MAXE 800000

// Scratch (no cudaMalloc allowed).
__device__ int   g_count[MAXN];          // per-dst edge count
__device__ int   g_rowptr[MAXN + 1];     // CSR row pointers
__device__ int   g_cursor[MAXN];         // placement cursors (copy of rowptr)
__device__ int   g_srcs[MAXE];           // src ids sorted by dst
__device__ uint4 g_Bhi4[(D * K2 * 2) / 16];   // [96][192] bf16 Wcat hi
__device__ uint4 g_Blo4[(D * K2 * 2) / 16];   // [96][192] bf16 Wcat lo

// ---------------------------------------------------------------------------
// helpers
// ---------------------------------------------------------------------------
__device__ __forceinline__ uint32_t smem_u32(const void* p) {
    uint32_t a;
    asm("{ .reg .u64 t; cvta.to.shared.u64 t, %1; cvt.u32.u64 %0, t; }"
        : "=r"(a) : "l"(p));
    return a;
}

#define LDSM_X4(r, addr)                                                      \
    asm volatile("ldmatrix.sync.aligned.m8n8.x4.shared.b16 "                  \
                 "{%0,%1,%2,%3}, [%4];"                                       \
                 : "=r"((r)[0]), "=r"((r)[1]), "=r"((r)[2]), "=r"((r)[3])     \
                 : "r"(addr))

__device__ __forceinline__ void mma_bf16(float* c, const uint32_t* a,
                                         uint32_t b0, uint32_t b1) {
    asm volatile(
        "mma.sync.aligned.m16n8k16.row.col.f32.bf16.bf16.f32 "
        "{%0,%1,%2,%3}, {%4,%5,%6,%7}, {%8,%9}, {%0,%1,%2,%3};"
        : "+f"(c[0]), "+f"(c[1]), "+f"(c[2]), "+f"(c[3])
        : "r"(a[0]), "r"(a[1]), "r"(a[2]), "r"(a[3]), "r"(b0), "r"(b1));
}

// ---------------------------------------------------------------------------
// 1) prep: zero counters + W = [Wl|Wr] bf16 hi/lo split
// ---------------------------------------------------------------------------
__global__ void prep_kernel(const float* __restrict__ Wl,
                            const float* __restrict__ Wr, int n)
{
    int idx = blockIdx.x * blockDim.x + threadIdx.x;
    if (idx < n) g_count[idx] = 0;
    if (idx < D * K2) {
        int r = idx / K2, k = idx % K2;
        float w = (k < D) ? Wl[r * D + k] : Wr[r * D + (k - D)];
        __nv_bfloat16 h = __float2bfloat16(w);
        reinterpret_cast<__nv_bfloat16*>(g_Bhi4)[idx] = h;
        reinterpret_cast<__nv_bfloat16*>(g_Blo4)[idx] =
            __float2bfloat16(w - __bfloat162float(h));
    }
}

// ---------------------------------------------------------------------------
// 2) histogram of dst
// ---------------------------------------------------------------------------
__global__ void hist_kernel(const int* __restrict__ ei, int E) {
    int i = blockIdx.x * blockDim.x + threadIdx.x;
    int st = gridDim.x * blockDim.x;
    for (int e = i; e < E; e += st)
        atomicAdd(&g_count[__ldg(ei + E + e)], 1);
}

// ---------------------------------------------------------------------------
// 3) exclusive scan (single block, 1024 threads, shfl two-level)
// ---------------------------------------------------------------------------
__global__ __launch_bounds__(1024) void scan_kernel(int n) {
    __shared__ int warpsum[32];
    int tid = threadIdx.x, lane = tid & 31, w = tid >> 5;
    int seg = (n + 1023) >> 10;
    int start = min(tid * seg, n);
    int end = min(start + seg, n);

    int s = 0;
    for (int i = start; i < end; ++i) s += g_count[i];

    int v = s;
#pragma unroll
    for (int o = 1; o < 32; o <<= 1) {
        int t = __shfl_up_sync(0xffffffffu, v, o);
        if (lane >= o) v += t;
    }
    if (lane == 31) warpsum[w] = v;
    __syncthreads();
    if (w == 0) {
        int ws = warpsum[lane];
#pragma unroll
        for (int o = 1; o < 32; o <<= 1) {
            int t = __shfl_up_sync(0xffffffffu, ws, o);
            if (lane >= o) ws += t;
        }
        warpsum[lane] = ws;
    }
    __syncthreads();

    int base = (w > 0) ? warpsum[w - 1] : 0;
    int run = base + v - s;                 // exclusive prefix at 'start'
    for (int i = start; i < end; ++i) {
        int c = g_count[i];
        g_rowptr[i] = run;
        g_cursor[i] = run;
        run += c;
    }
    if (end == n) g_rowptr[n] = run;        // all such threads write the total
}

// ---------------------------------------------------------------------------
// 4) place edges into CSR order
// ---------------------------------------------------------------------------
__global__ void place_kernel(const int* __restrict__ ei, int E) {
    int i = blockIdx.x * blockDim.x + threadIdx.x;
    int st = gridDim.x * blockDim.x;
    for (int e = i; e < E; e += st) {
        int src = __ldg(ei + e);
        int dst = __ldg(ei + E + e);
        int p = atomicAdd(&g_cursor[dst], 1);
        g_srcs[p] = src;
    }
}

// ---------------------------------------------------------------------------
// 5) fused gather + GEMM:  out = relu([mean_nbr | x] @ [Wl|Wr]^T + bl)
//    CTA: 128 nodes x 96 outputs, 256 threads. Gather-mean built in-CTA from
//    CSR (no g_agg round-trip). bf16 hi/lo x3-pass HMMA, fp32 accum.
// ---------------------------------------------------------------------------
#define RS    400                  // smem row stride bytes (200 bf16)
#define SM_AHI 0
#define SM_ALO 51200               // 128*400
#define SM_BHI 102400
#define SM_BLO 140800              // + 96*400
#define SM_TOTAL 179200

__device__ __forceinline__ void st_split(char* smem, int r, int col, float v) {
    __nv_bfloat16 h = __float2bfloat16(v);
    __nv_bfloat16 l = __float2bfloat16(v - __bfloat162float(h));
    *reinterpret_cast<__nv_bfloat16*>(smem + SM_AHI + r * RS + col * 2) = h;
    *reinterpret_cast<__nv_bfloat16*>(smem + SM_ALO + r * RS + col * 2) = l;
}

__global__ __launch_bounds__(256, 1) void fused_gemm_kernel(
    const float* __restrict__ x, const float* __restrict__ bl,
    float* __restrict__ out, int N)
{
    extern __shared__ char smem[];
    const int tid  = threadIdx.x;
    const int wid  = tid >> 5;
    const int lane = tid & 31;
    const int m0   = blockIdx.x * 128;
    const int mg   = wid & 3;        // m block (32 rows)
    const int ng   = wid >> 2;       // n block (48 cols)

    // --- load W tiles (bf16, pre-split) into padded smem ---
    for (int l = tid; l < 2304; l += 256) {               // 96 rows x 24 uint4
        int n = l / 24, q = l % 24;
        int so = n * RS + q * 16;
        *reinterpret_cast<uint4*>(smem + SM_BHI + so) = g_Bhi4[n * 24 + q];
        *reinterpret_cast<uint4*>(smem + SM_BLO + so) = g_Blo4[n * 24 + q];
    }

    // --- gather-mean + convert A: warp w handles nodes w*16 .. w*16+15 ---
    for (int t = 0; t < 16; ++t) {
        int r = wid * 16 + t;
        int node = m0 + r;
        float s0 = 0.f, s1 = 0.f, s2 = 0.f;
        float xv0 = 0.f, xv1 = 0.f, xv2 = 0.f;
        float inv = 1.f;
        if (node < N) {
            int rp0 = __ldg(g_rowptr + node);
            int rp1 = __ldg(g_rowptr + node + 1);
            inv = 1.0f / fmaxf((float)(rp1 - rp0), 1.0f);
            int e = rp0;
            while (e < rp1) {
                int cnt = min(rp1 - e, 32);
                int my = (lane < cnt) ? __ldg(g_srcs + e + lane) : 0;
                int j = 0;
                for (; j + 4 <= cnt; j += 4) {
                    int sA = __shfl_sync(0xffffffffu, my, j);
                    int sB = __shfl_sync(0xffffffffu, my, j + 1);
                    int sC = __shfl_sync(0xffffffffu, my, j + 2);
                    int sD = __shfl_sync(0xffffffffu, my, j + 3);
                    const float* pA = x + (size_t)sA * D;
                    const float* pB = x + (size_t)sB * D;
                    const float* pC = x + (size_t)sC * D;
                    const float* pD = x + (size_t)sD * D;
                    float a0 = __ldg(pA + lane), a1 = __ldg(pA + 32 + lane), a2 = __ldg(pA + 64 + lane);
                    float b0 = __ldg(pB + lane), b1 = __ldg(pB + 32 + lane), b2 = __ldg(pB + 64 + lane);
                    float c0 = __ldg(pC + lane), c1 = __ldg(pC + 32 + lane), c2 = __ldg(pC + 64 + lane);
                    float d0 = __ldg(pD + lane), d1 = __ldg(pD + 32 + lane), d2 = __ldg(pD + 64 + lane);
                    s0 += (a0 + b0) + (c0 + d0);
                    s1 += (a1 + b1) + (c1 + d1);
                    s2 += (a2 + b2) + (c2 + d2);
                }
                for (; j < cnt; ++j) {
                    int sA = __shfl_sync(0xffffffffu, my, j);
                    const float* pA = x + (size_t)sA * D;
                    s0 += __ldg(pA + lane);
                    s1 += __ldg(pA + 32 + lane);
                    s2 += __ldg(pA + 64 + lane);
                }
                e += cnt;
            }
            const float* xn = x + (size_t)node * D;
            xv0 = __ldg(xn + lane);
            xv1 = __ldg(xn + 32 + lane);
            xv2 = __ldg(xn + 64 + lane);
        }
        st_split(smem, r, lane,       s0 * inv);
        st_split(smem, r, 32 + lane,  s1 * inv);
        st_split(smem, r, 64 + lane,  s2 * inv);
        st_split(smem, r, 96 + lane,  xv0);
        st_split(smem, r, 128 + lane, xv1);
        st_split(smem, r, 160 + lane, xv2);
    }
    __syncthreads();

    // --- mainloop (unchanged from R4) ---
    float acc[2][6][4];
#pragma unroll
    for (int i = 0; i < 2; ++i)
#pragma unroll
        for (int j = 0; j < 6; ++j)
#pragma unroll
            for (int r = 0; r < 4; ++r) acc[i][j][r] = 0.f;

    const int arow  = mg * 32 + (lane & 7) + ((lane >> 3) & 1) * 8;
    const int akoff = (lane >> 4) << 3;
    const int brow  = ng * 48 + (lane & 7) + ((lane >> 4) << 3);
    const int bkoff = ((lane >> 3) & 1) << 3;
    const uint32_t sbase = smem_u32(smem);

#pragma unroll 1
    for (int p = 0; p < 3; ++p) {
        const uint32_t Ab = sbase + (p == 1 ? SM_ALO : SM_AHI);
        const uint32_t Bb = sbase + (p == 2 ? SM_BLO : SM_BHI);
        const uint32_t aAddr = Ab + arow * RS + akoff * 2;
        const uint32_t bAddr = Bb + brow * RS + bkoff * 2;

#pragma unroll
        for (int ks = 0; ks < 12; ++ks) {
            const int kb = ks * 32;               // 16 bf16 = 32 B
            uint32_t a[2][4];
            LDSM_X4(a[0], aAddr + kb);
            LDSM_X4(a[1], aAddr + 16 * RS + kb);
            uint32_t b[3][4];
            LDSM_X4(b[0], bAddr + kb);
            LDSM_X4(b[1], bAddr + 16 * RS + kb);
            LDSM_X4(b[2], bAddr + 32 * RS + kb);
#pragma unroll
            for (int i = 0; i < 2; ++i)
#pragma unroll
                for (int j = 0; j < 6; ++j)
                    mma_bf16(acc[i][j], a[i], b[j >> 1][(j & 1) * 2],
                             b[j >> 1][(j & 1) * 2 + 1]);
        }
    }

    // --- epilogue: bias + relu + float2 stores ---
    const int lrow = lane >> 2;
    const int lcol = (lane & 3) * 2;
#pragma unroll
    for (int i = 0; i < 2; ++i) {
#pragma unroll
        for (int j = 0; j < 6; ++j) {
            int col = ng * 48 + j * 8 + lcol;
            float b0 = __ldg(bl + col);
            float b1 = __ldg(bl + col + 1);
            int row0 = m0 + mg * 32 + i * 16 + lrow;
            if (row0 < N) {
                float2 o = make_float2(fmaxf(acc[i][j][0] + b0, 0.f),
                                       fmaxf(acc[i][j][1] + b1, 0.f));
                *reinterpret_cast<float2*>(out + (size_t)row0 * D + col) = o;
            }
            int row1 = row0 + 8;
            if (row1 < N) {
                float2 o = make_float2(fmaxf(acc[i][j][2] + b0, 0.f),
                                       fmaxf(acc[i][j][3] + b1, 0.f));
                *reinterpret_cast<float2*>(out + (size_t)row1 * D + col) = o;
            }
        }
    }
}

// ---------------------------------------------------------------------------
// kernel_launch
// ---------------------------------------------------------------------------
extern "C" void kernel_launch(void* const* d_in, const int* in_sizes, int n_in,
                              void* d_out, int out_size)
{
    const float* x  = (const float*)d_in[0];
    const int*   ei = (const int*)  d_in[1];
    const float* Wl = (const float*)d_in[2];
    const float* bl = (const float*)d_in[3];
    const float* Wr = (const float*)d_in[4];
    float* out = (float*)d_out;

    const int N = in_sizes[0] / D;
    const int E = in_sizes[1] / 2;

    cudaFuncSetAttribute(fused_gemm_kernel,
                         cudaFuncAttributeMaxDynamicSharedMemorySize, SM_TOTAL);

    int prep_elems = (N > D * K2) ? N : D * K2;
    prep_kernel<<<(prep_elems + 255) / 256, 256>>>(Wl, Wr, N);
    hist_kernel<<<1024, 256>>>(ei, E);
    scan_kernel<<<1, 1024>>>(N);
    place_kernel<<<1024, 256>>>(ei, E);
    fused_gemm_kernel<<<(N + 127) / 128, 256, SM_TOTAL>>>(x, bl, out, N);
}

// round 6
// speedup vs baseline: 1.6198x; 1.6198x over previous
#include <cuda_runtime.h>
#include <cuda_bf16.h>
#include <cstdint>

// Problem constants.
#define D    96      // D_IN == D_OUT
#define K2   192     // concat K = 2*D
#define MAXN 50000

// Scratch (no cudaMalloc allowed). uint4 typing guarantees 16B alignment.
__device__ float g_agg[(size_t)MAXN * D];        // neighbor-sum
__device__ float g_deg[MAXN];                    // degree -> 1/max(deg,1)
__device__ uint4 g_Bhi4[(D * K2 * 2) / 16];      // [96][192] bf16 Wcat hi
__device__ uint4 g_Blo4[(D * K2 * 2) / 16];      // [96][192] bf16 Wcat lo

// ---------------------------------------------------------------------------
// helpers
// ---------------------------------------------------------------------------
__device__ __forceinline__ uint32_t smem_u32(const void* p) {
    uint32_t a;
    asm("{ .reg .u64 t; cvta.to.shared.u64 t, %1; cvt.u32.u64 %0, t; }"
        : "=r"(a) : "l"(p));
    return a;
}

__device__ __forceinline__ uint32_t pack_bf16x2(float a, float b) {
    uint32_t r;
    asm("cvt.rn.bf16x2.f32 %0, %1, %2;" : "=r"(r) : "f"(b), "f"(a));
    return r;
}

#define LDSM_X4(r, addr)                                                      \
    asm volatile("ldmatrix.sync.aligned.m8n8.x4.shared.b16 "                  \
                 "{%0,%1,%2,%3}, [%4];"                                       \
                 : "=r"((r)[0]), "=r"((r)[1]), "=r"((r)[2]), "=r"((r)[3])     \
                 : "r"(addr))

__device__ __forceinline__ void mma_bf16(float* c, const uint32_t* a,
                                         uint32_t b0, uint32_t b1) {
    asm volatile(
        "mma.sync.aligned.m16n8k16.row.col.f32.bf16.bf16.f32 "
        "{%0,%1,%2,%3}, {%4,%5,%6,%7}, {%8,%9}, {%0,%1,%2,%3};"
        : "+f"(c[0]), "+f"(c[1]), "+f"(c[2]), "+f"(c[3])
        : "r"(a[0]), "r"(a[1]), "r"(a[2]), "r"(a[3]), "r"(b0), "r"(b1));
}

// ---------------------------------------------------------------------------
// 0) prep: zero agg+deg, split W = [Wl|Wr] into bf16 hi/lo
// ---------------------------------------------------------------------------
__global__ void prep_kernel(const float* __restrict__ Wl,
                            const float* __restrict__ Wr,
                            int n_agg4, int n_deg)
{
    int idx = blockIdx.x * blockDim.x + threadIdx.x;
    int stride = gridDim.x * blockDim.x;
    float4* a4 = reinterpret_cast<float4*>(g_agg);
    for (int i = idx; i < n_agg4; i += stride)
        a4[i] = make_float4(0.f, 0.f, 0.f, 0.f);
    for (int i = idx; i < n_deg; i += stride)
        g_deg[i] = 0.f;
    for (int i = idx; i < D * K2; i += stride) {
        int r = i / K2, k = i % K2;
        float w = (k < D) ? Wl[r * D + k] : Wr[r * D + (k - D)];
        __nv_bfloat16 h = __float2bfloat16(w);
        reinterpret_cast<__nv_bfloat16*>(g_Bhi4)[i] = h;
        reinterpret_cast<__nv_bfloat16*>(g_Blo4)[i] =
            __float2bfloat16(w - __bfloat162float(h));
    }
}

// ---------------------------------------------------------------------------
// 1) scatter: agg[dst] += x[src]; deg[dst] += 1   (red.global.add.v4.f32)
// ---------------------------------------------------------------------------
__global__ __launch_bounds__(192) void scatter_kernel(
    const float* __restrict__ x, const int* __restrict__ ei, int E)
{
    int e = blockIdx.x * 8 + threadIdx.y;
    if (e >= E) return;
    int c = threadIdx.x;                 // 0..23
    int src = __ldg(ei + e);
    int dst = __ldg(ei + E + e);

    float4 v = *reinterpret_cast<const float4*>(x + (size_t)src * D + c * 4);
    float* p = g_agg + (size_t)dst * D + c * 4;
    asm volatile("red.global.add.v4.f32 [%0], {%1,%2,%3,%4};"
                 :: "l"(p), "f"(v.x), "f"(v.y), "f"(v.z), "f"(v.w)
                 : "memory");
    if (c == 0) atomicAdd(g_deg + dst, 1.0f);
}

// ---------------------------------------------------------------------------
// 2) invert degree
// ---------------------------------------------------------------------------
__global__ void recip_kernel(int n) {
    int i = blockIdx.x * blockDim.x + threadIdx.x;
    if (i < n) g_deg[i] = 1.0f / fmaxf(g_deg[i], 1.0f);
}

// ---------------------------------------------------------------------------
// 3) GEMM via mma.sync bf16: out = relu([agg*invdeg | x] @ [Wl|Wr]^T + bl)
//    CTA: 64 nodes x 96 outputs, 128 threads = 4 warps (warp tile 16x96).
//    smem 89.6 KB -> 2 CTAs/SM (phase overlap across CTAs).
//    Passes: load Bhi -> (Ahi*B, Alo*B) -> overwrite B with Blo -> (Ahi*B).
// ---------------------------------------------------------------------------
#define RS     400                 // smem row stride bytes (200 bf16)
#define SM_AHI 0
#define SM_ALO 25600               // 64*400
#define SM_B   51200               // + 64*400
#define SM_TOTAL 89600             // + 96*400

__global__ __launch_bounds__(128, 2) void fused_gemm_kernel(
    const float* __restrict__ x, const float* __restrict__ bl,
    float* __restrict__ out, int N)
{
    extern __shared__ char smem[];
    const int tid  = threadIdx.x;
    const int wid  = tid >> 5;      // 0..3
    const int lane = tid & 31;
    const int m0   = blockIdx.x * 64;

    // --- load Bhi into smem B ---
    for (int l = tid; l < 2304; l += 128) {               // 96 rows x 24 uint4
        int n = l / 24, q = l % 24;
        *reinterpret_cast<uint4*>(smem + SM_B + n * RS + q * 16) =
            g_Bhi4[n * 24 + q];
    }

    // --- load + convert A: 64 rows x 48 float4 slots ---
    for (int l = tid; l < 3072; l += 128) {
        int r = l / 48, q = l % 48;
        int node = m0 + r;
        float4 v = make_float4(0.f, 0.f, 0.f, 0.f);
        int kcol;
        if (q < 24) {
            kcol = q * 4;
            if (node < N) {
                v = *reinterpret_cast<const float4*>(g_agg + (size_t)node * D + kcol);
                float inv = g_deg[node];
                v.x *= inv; v.y *= inv; v.z *= inv; v.w *= inv;
            }
        } else {
            kcol = 96 + (q - 24) * 4;
            if (node < N)
                v = *reinterpret_cast<const float4*>(x + (size_t)node * D + (q - 24) * 4);
        }
        uint32_t h01 = pack_bf16x2(v.x, v.y);
        uint32_t h23 = pack_bf16x2(v.z, v.w);
        float r0 = v.x - __uint_as_float(h01 << 16);
        float r1 = v.y - __uint_as_float(h01 & 0xffff0000u);
        float r2 = v.z - __uint_as_float(h23 << 16);
        float r3 = v.w - __uint_as_float(h23 & 0xffff0000u);
        uint32_t l01 = pack_bf16x2(r0, r1);
        uint32_t l23 = pack_bf16x2(r2, r3);
        int so = r * RS + kcol * 2;
        *reinterpret_cast<uint2*>(smem + SM_AHI + so) = make_uint2(h01, h23);
        *reinterpret_cast<uint2*>(smem + SM_ALO + so) = make_uint2(l01, l23);
    }
    __syncthreads();

    // --- accumulators: warp tile 16 x 96 = 12 n8-frags x 4 ---
    float acc[12][4];
#pragma unroll
    for (int j = 0; j < 12; ++j)
#pragma unroll
        for (int r = 0; r < 4; ++r) acc[j][r] = 0.f;

    // ldmatrix lane addressing (R4-validated layout)
    const int arow  = wid * 16 + (lane & 7) + ((lane >> 3) & 1) * 8;
    const int akoff = (lane >> 4) << 3;
    const int brow  = (lane & 7) + ((lane >> 4) << 3);
    const int bkoff = ((lane >> 3) & 1) << 3;
    const uint32_t sbase = smem_u32(smem);
    const uint32_t aAddrH = sbase + SM_AHI + arow * RS + akoff * 2;
    const uint32_t aAddrL = sbase + SM_ALO + arow * RS + akoff * 2;
    const uint32_t bAddr0 = sbase + SM_B + brow * RS + bkoff * 2;

#pragma unroll 1
    for (int p = 0; p < 3; ++p) {
        if (p == 2) {
            // overwrite B with Blo
            __syncthreads();
            for (int l = tid; l < 2304; l += 128) {
                int n = l / 24, q = l % 24;
                *reinterpret_cast<uint4*>(smem + SM_B + n * RS + q * 16) =
                    g_Blo4[n * 24 + q];
            }
            __syncthreads();
        }
        const uint32_t aAddr = (p == 1) ? aAddrL : aAddrH;

#pragma unroll
        for (int ks = 0; ks < 12; ++ks) {
            const int kb = ks * 32;               // 16 bf16 = 32 B
            uint32_t a[4];
            LDSM_X4(a, aAddr + kb);
            uint32_t b[6][4];
#pragma unroll
            for (int q = 0; q < 6; ++q)
                LDSM_X4(b[q], bAddr0 + q * 16 * RS + kb);
#pragma unroll
            for (int j = 0; j < 12; ++j)
                mma_bf16(acc[j], a, b[j >> 1][(j & 1) * 2],
                         b[j >> 1][(j & 1) * 2 + 1]);
        }
    }

    // --- epilogue: bias + relu + float2 stores ---
    const int lrow = lane >> 2;
    const int lcol = (lane & 3) * 2;
#pragma unroll
    for (int j = 0; j < 12; ++j) {
        int col = j * 8 + lcol;
        float b0 = __ldg(bl + col);
        float b1 = __ldg(bl + col + 1);
        int row0 = m0 + wid * 16 + lrow;
        if (row0 < N) {
            float2 o = make_float2(fmaxf(acc[j][0] + b0, 0.f),
                                   fmaxf(acc[j][1] + b1, 0.f));
            *reinterpret_cast<float2*>(out + (size_t)row0 * D + col) = o;
        }
        int row1 = row0 + 8;
        if (row1 < N) {
            float2 o = make_float2(fmaxf(acc[j][2] + b0, 0.f),
                                   fmaxf(acc[j][3] + b1, 0.f));
            *reinterpret_cast<float2*>(out + (size_t)row1 * D + col) = o;
        }
    }
}

// ---------------------------------------------------------------------------
// kernel_launch
// ---------------------------------------------------------------------------
extern "C" void kernel_launch(void* const* d_in, const int* in_sizes, int n_in,
                              void* d_out, int out_size)
{
    const float* x  = (const float*)d_in[0];
    const int*   ei = (const int*)  d_in[1];
    const float* Wl = (const float*)d_in[2];
    const float* bl = (const float*)d_in[3];
    const float* Wr = (const float*)d_in[4];
    float* out = (float*)d_out;

    const int N = in_sizes[0] / D;
    const int E = in_sizes[1] / 2;

    cudaFuncSetAttribute(fused_gemm_kernel,
                         cudaFuncAttributeMaxDynamicSharedMemorySize, SM_TOTAL);

    prep_kernel<<<2048, 256>>>(Wl, Wr, (N * D) / 4, N);

    dim3 sblk(24, 8);
    scatter_kernel<<<(E + 7) / 8, sblk>>>(x, ei, E);

    recip_kernel<<<(N + 255) / 256, 256>>>(N);

    fused_gemm_kernel<<<(N + 63) / 64, 128, SM_TOTAL>>>(x, bl, out, N);
}

// round 7
// speedup vs baseline: 2.0252x; 1.2503x over previous
#include <cuda_runtime.h>
#include <cuda_bf16.h>
#include <cstdint>

// Problem constants.
#define D    96      // D_IN == D_OUT
#define K2   192     // concat K = 2*D
#define MAXN 50000

// Scratch (no cudaMalloc allowed). uint4 typing guarantees 16B alignment.
__device__ float g_agg[(size_t)MAXN * D];        // neighbor-sum
__device__ float g_deg[MAXN];                    // degree -> 1/max(deg,1)
__device__ uint4 g_Bhi4[(D * K2 * 2) / 16];      // [96][192] bf16 Wcat hi
__device__ uint4 g_Blo4[(D * K2 * 2) / 16];      // [96][192] bf16 Wcat lo

// ---------------------------------------------------------------------------
// helpers
// ---------------------------------------------------------------------------
__device__ __forceinline__ uint32_t smem_u32(const void* p) {
    uint32_t a;
    asm("{ .reg .u64 t; cvta.to.shared.u64 t, %1; cvt.u32.u64 %0, t; }"
        : "=r"(a) : "l"(p));
    return a;
}

// pack two f32 into bf16x2 (lo half = a, hi half = b)
__device__ __forceinline__ uint32_t pack_bf16x2(float a, float b) {
    uint32_t r;
    asm("cvt.rn.bf16x2.f32 %0, %1, %2;" : "=r"(r) : "f"(b), "f"(a));
    return r;
}

#define LDSM_X4(r, addr)                                                      \
    asm volatile("ldmatrix.sync.aligned.m8n8.x4.shared.b16 "                  \
                 "{%0,%1,%2,%3}, [%4];"                                       \
                 : "=r"((r)[0]), "=r"((r)[1]), "=r"((r)[2]), "=r"((r)[3])     \
                 : "r"(addr))

__device__ __forceinline__ void mma_bf16(float* c, const uint32_t* a,
                                         uint32_t b0, uint32_t b1) {
    asm volatile(
        "mma.sync.aligned.m16n8k16.row.col.f32.bf16.bf16.f32 "
        "{%0,%1,%2,%3}, {%4,%5,%6,%7}, {%8,%9}, {%0,%1,%2,%3};"
        : "+f"(c[0]), "+f"(c[1]), "+f"(c[2]), "+f"(c[3])
        : "r"(a[0]), "r"(a[1]), "r"(a[2]), "r"(a[3]), "r"(b0), "r"(b1));
}

// ---------------------------------------------------------------------------
// 0) prep: zero agg+deg, split W = [Wl|Wr] into bf16 hi/lo
// ---------------------------------------------------------------------------
__global__ void prep_kernel(const float* __restrict__ Wl,
                            const float* __restrict__ Wr,
                            int n_agg4, int n_deg)
{
    int idx = blockIdx.x * blockDim.x + threadIdx.x;
    int stride = gridDim.x * blockDim.x;
    float4* a4 = reinterpret_cast<float4*>(g_agg);
    for (int i = idx; i < n_agg4; i += stride)
        a4[i] = make_float4(0.f, 0.f, 0.f, 0.f);
    for (int i = idx; i < n_deg; i += stride)
        g_deg[i] = 0.f;
    for (int i = idx; i < D * K2; i += stride) {
        int r = i / K2, k = i % K2;
        float w = (k < D) ? Wl[r * D + k] : Wr[r * D + (k - D)];
        __nv_bfloat16 h = __float2bfloat16(w);
        reinterpret_cast<__nv_bfloat16*>(g_Bhi4)[i] = h;
        reinterpret_cast<__nv_bfloat16*>(g_Blo4)[i] =
            __float2bfloat16(w - __bfloat162float(h));
    }
}

// ---------------------------------------------------------------------------
// 1) scatter: agg[dst] += x[src]; deg[dst] += 1   (red.global.add.v4.f32)
// ---------------------------------------------------------------------------
__global__ __launch_bounds__(192) void scatter_kernel(
    const float* __restrict__ x, const int* __restrict__ ei, int E)
{
    int e = blockIdx.x * 8 + threadIdx.y;
    if (e >= E) return;
    int c = threadIdx.x;                 // 0..23
    int src = __ldg(ei + e);
    int dst = __ldg(ei + E + e);

    float4 v = *reinterpret_cast<const float4*>(x + (size_t)src * D + c * 4);
    float* p = g_agg + (size_t)dst * D + c * 4;
    asm volatile("red.global.add.v4.f32 [%0], {%1,%2,%3,%4};"
                 :: "l"(p), "f"(v.x), "f"(v.y), "f"(v.z), "f"(v.w)
                 : "memory");
    if (c == 0) atomicAdd(g_deg + dst, 1.0f);
}

// ---------------------------------------------------------------------------
// 2) invert degree
// ---------------------------------------------------------------------------
__global__ void recip_kernel(int n) {
    int i = blockIdx.x * blockDim.x + threadIdx.x;
    if (i < n) g_deg[i] = 1.0f / fmaxf(g_deg[i], 1.0f);
}

// ---------------------------------------------------------------------------
// 3) GEMM: out = relu([agg*invdeg | x] @ [Wl|Wr]^T + bl)
//    A fragments loaded DIRECTLY from global (no smem A), converted to bf16
//    hi/lo in registers. Only B lives in smem: one 36.9 KB buffer (RS=384,
//    XOR 16B-chunk swizzle for conflict-free ldmatrix), timeshared hi -> lo.
//    CTA: 128 threads = 4 warps, each warp owns 16 rows x 96 cols.
//    Phase A (Bhi): per k-step  A_hi*B + A_lo*B  (24 MMA).
//    Phase B (Blo): per k-step  A_hi*B           (12 MMA).
// ---------------------------------------------------------------------------
#define BRS 384                      // B row stride bytes (192 bf16)

// swizzled 16B-chunk offset within a row
__device__ __forceinline__ int bswz(int row, int chunk) {
    return ((chunk & ~7) | ((chunk ^ row) & 7)) << 4;
}

struct AFrag { uint32_t hi[4], lo[4]; };

// Load one k-step's A fragments straight from global, with bf16 hi/lo split.
template <bool WANT_LO>
__device__ __forceinline__ void load_afrag(
    const float* __restrict__ p0, const float* __restrict__ p1,  // row ptrs (agg or x)
    float inv0, float inv1, int col, bool v0ok, bool v1ok, AFrag& f)
{
    float2 z = make_float2(0.f, 0.f);
    float2 v00 = v0ok ? __ldg(reinterpret_cast<const float2*>(p0 + col))     : z;
    float2 v01 = v0ok ? __ldg(reinterpret_cast<const float2*>(p0 + col + 8)) : z;
    float2 v10 = v1ok ? __ldg(reinterpret_cast<const float2*>(p1 + col))     : z;
    float2 v11 = v1ok ? __ldg(reinterpret_cast<const float2*>(p1 + col + 8)) : z;
    v00.x *= inv0; v00.y *= inv0; v01.x *= inv0; v01.y *= inv0;
    v10.x *= inv1; v10.y *= inv1; v11.x *= inv1; v11.y *= inv1;

    f.hi[0] = pack_bf16x2(v00.x, v00.y);
    f.hi[1] = pack_bf16x2(v10.x, v10.y);
    f.hi[2] = pack_bf16x2(v01.x, v01.y);
    f.hi[3] = pack_bf16x2(v11.x, v11.y);
    if (WANT_LO) {
        f.lo[0] = pack_bf16x2(v00.x - __uint_as_float(f.hi[0] << 16),
                              v00.y - __uint_as_float(f.hi[0] & 0xffff0000u));
        f.lo[1] = pack_bf16x2(v10.x - __uint_as_float(f.hi[1] << 16),
                              v10.y - __uint_as_float(f.hi[1] & 0xffff0000u));
        f.lo[2] = pack_bf16x2(v01.x - __uint_as_float(f.hi[2] << 16),
                              v01.y - __uint_as_float(f.hi[2] & 0xffff0000u));
        f.lo[3] = pack_bf16x2(v11.x - __uint_as_float(f.hi[3] << 16),
                              v11.y - __uint_as_float(f.hi[3] & 0xffff0000u));
    }
}

__global__ __launch_bounds__(128, 4) void fused_gemm_kernel(
    const float* __restrict__ x, const float* __restrict__ bl,
    float* __restrict__ out, int N)
{
    __shared__ char smem[96 * BRS];      // single B buffer, 36.9 KB

    const int tid  = threadIdx.x;
    const int wid  = tid >> 5;           // 0..3
    const int lane = tid & 31;
    const int m0   = blockIdx.x * 64;
    const int mbase = m0 + wid * 16;

    // --- stage Bhi (swizzled) ---
    for (int l = tid; l < 2304; l += 128) {
        int n = l / 24, q = l % 24;
        *reinterpret_cast<uint4*>(smem + n * BRS + bswz(n, q)) = g_Bhi4[l];
    }

    // per-lane A addressing (m16n8k16 fragment map)
    const int g = lane >> 2, t = lane & 3;
    const int r0 = mbase + g, r1 = r0 + 8;
    const bool ok0 = r0 < N, ok1 = r1 < N;
    const float inv0 = ok0 ? __ldg(g_deg + r0) : 1.f;
    const float inv1 = ok1 ? __ldg(g_deg + r1) : 1.f;
    const float* aggp0 = g_agg + (size_t)(ok0 ? r0 : 0) * D;
    const float* aggp1 = g_agg + (size_t)(ok1 ? r1 : 0) * D;
    const float* xp0   = x     + (size_t)(ok0 ? r0 : 0) * D;
    const float* xp1   = x     + (size_t)(ok1 ? r1 : 0) * D;

    // per-lane B ldmatrix addressing
    const int lrow8  = lane & 7;
    const int brow   = lrow8 + ((lane >> 4) << 3);
    const int bksel  = (lane >> 3) & 1;                 // 0/1: k 0-7 / 8-15
    const uint32_t sb = smem_u32(smem);

    float acc[12][4];
#pragma unroll
    for (int j = 0; j < 12; ++j)
#pragma unroll
        for (int r = 0; r < 4; ++r) acc[j][r] = 0.f;

    __syncthreads();

    // ===== Phase A: B = Bhi; per k-step do A_hi*B + A_lo*B =====
#pragma unroll
    for (int ks = 0; ks < 12; ++ks) {
        AFrag f;
        const int c2 = ks * 16 + 2 * t;
        if (ks < 6)
            load_afrag<true>(aggp0, aggp1, inv0, inv1, c2, ok0, ok1, f);
        else
            load_afrag<true>(xp0, xp1, 1.f, 1.f, c2 - 96, ok0, ok1, f);

        const int ch = 2 * ks + bksel;
        const uint32_t bAddr = sb + brow * BRS + bswz(lrow8, ch);
        uint32_t b[6][4];
#pragma unroll
        for (int q = 0; q < 6; ++q)
            LDSM_X4(b[q], bAddr + q * 16 * BRS);
#pragma unroll
        for (int j = 0; j < 12; ++j)
            mma_bf16(acc[j], f.hi, b[j >> 1][(j & 1) * 2], b[j >> 1][(j & 1) * 2 + 1]);
#pragma unroll
        for (int j = 0; j < 12; ++j)
            mma_bf16(acc[j], f.lo, b[j >> 1][(j & 1) * 2], b[j >> 1][(j & 1) * 2 + 1]);
    }

    // ===== swap in Blo =====
    __syncthreads();
    for (int l = tid; l < 2304; l += 128) {
        int n = l / 24, q = l % 24;
        *reinterpret_cast<uint4*>(smem + n * BRS + bswz(n, q)) = g_Blo4[l];
    }
    __syncthreads();

    // ===== Phase B: B = Blo; per k-step do A_hi*B =====
#pragma unroll
    for (int ks = 0; ks < 12; ++ks) {
        AFrag f;
        const int c2 = ks * 16 + 2 * t;
        if (ks < 6)
            load_afrag<false>(aggp0, aggp1, inv0, inv1, c2, ok0, ok1, f);
        else
            load_afrag<false>(xp0, xp1, 1.f, 1.f, c2 - 96, ok0, ok1, f);

        const int ch = 2 * ks + bksel;
        const uint32_t bAddr = sb + brow * BRS + bswz(lrow8, ch);
        uint32_t b[6][4];
#pragma unroll
        for (int q = 0; q < 6; ++q)
            LDSM_X4(b[q], bAddr + q * 16 * BRS);
#pragma unroll
        for (int j = 0; j < 12; ++j)
            mma_bf16(acc[j], f.hi, b[j >> 1][(j & 1) * 2], b[j >> 1][(j & 1) * 2 + 1]);
    }

    // --- epilogue: bias + relu + float2 stores ---
    const int erow = lane >> 2;
    const int ecol = (lane & 3) * 2;
#pragma unroll
    for (int j = 0; j < 12; ++j) {
        int col = j * 8 + ecol;
        float b0 = __ldg(bl + col);
        float b1 = __ldg(bl + col + 1);
        int row0 = mbase + erow;
        if (row0 < N) {
            float2 o = make_float2(fmaxf(acc[j][0] + b0, 0.f),
                                   fmaxf(acc[j][1] + b1, 0.f));
            *reinterpret_cast<float2*>(out + (size_t)row0 * D + col) = o;
        }
        int row1 = row0 + 8;
        if (row1 < N) {
            float2 o = make_float2(fmaxf(acc[j][2] + b0, 0.f),
                                   fmaxf(acc[j][3] + b1, 0.f));
            *reinterpret_cast<float2*>(out + (size_t)row1 * D + col) = o;
        }
    }
}

// ---------------------------------------------------------------------------
// kernel_launch
// ---------------------------------------------------------------------------
extern "C" void kernel_launch(void* const* d_in, const int* in_sizes, int n_in,
                              void* d_out, int out_size)
{
    const float* x  = (const float*)d_in[0];
    const int*   ei = (const int*)  d_in[1];
    const float* Wl = (const float*)d_in[2];
    const float* bl = (const float*)d_in[3];
    const float* Wr = (const float*)d_in[4];
    float* out = (float*)d_out;

    const int N = in_sizes[0] / D;
    const int E = in_sizes[1] / 2;

    prep_kernel<<<2048, 256>>>(Wl, Wr, (N * D) / 4, N);

    dim3 sblk(24, 8);
    scatter_kernel<<<(E + 7) / 8, sblk>>>(x, ei, E);

    recip_kernel<<<(N + 255) / 256, 256>>>(N);

    fused_gemm_kernel<<<(N + 63) / 64, 128>>>(x, bl, out, N);
}

// round 8
// speedup vs baseline: 2.4057x; 1.1879x over previous
#include <cuda_runtime.h>
#include <cuda_bf16.h>
#include <cstdint>

// Problem constants.
#define D    96      // D_IN == D_OUT
#define K2   192     // concat K = 2*D
#define MAXN 50000

// Scratch (no cudaMalloc allowed). uint4 typing guarantees 16B alignment.
__device__ float g_agg[(size_t)MAXN * D];        // neighbor-sum
__device__ float g_deg[MAXN];                    // degree -> 1/max(deg,1)
__device__ uint4 g_Bhi4[(D * K2 * 2) / 16];      // [96][192] bf16 Wcat hi
__device__ uint4 g_Blo4[(D * K2 * 2) / 16];      // [96][192] bf16 Wcat lo

// ---------------------------------------------------------------------------
// helpers
// ---------------------------------------------------------------------------
__device__ __forceinline__ uint32_t smem_u32(const void* p) {
    uint32_t a;
    asm("{ .reg .u64 t; cvta.to.shared.u64 t, %1; cvt.u32.u64 %0, t; }"
        : "=r"(a) : "l"(p));
    return a;
}

// pack two f32 into bf16x2 (lo half = a, hi half = b)
__device__ __forceinline__ uint32_t pack_bf16x2(float a, float b) {
    uint32_t r;
    asm("cvt.rn.bf16x2.f32 %0, %1, %2;" : "=r"(r) : "f"(b), "f"(a));
    return r;
}

#define LDSM_X4(r, addr)                                                      \
    asm volatile("ldmatrix.sync.aligned.m8n8.x4.shared.b16 "                  \
                 "{%0,%1,%2,%3}, [%4];"                                       \
                 : "=r"((r)[0]), "=r"((r)[1]), "=r"((r)[2]), "=r"((r)[3])     \
                 : "r"(addr))

__device__ __forceinline__ void mma_bf16(float* c, const uint32_t* a,
                                         uint32_t b0, uint32_t b1) {
    asm volatile(
        "mma.sync.aligned.m16n8k16.row.col.f32.bf16.bf16.f32 "
        "{%0,%1,%2,%3}, {%4,%5,%6,%7}, {%8,%9}, {%0,%1,%2,%3};"
        : "+f"(c[0]), "+f"(c[1]), "+f"(c[2]), "+f"(c[3])
        : "r"(a[0]), "r"(a[1]), "r"(a[2]), "r"(a[3]), "r"(b0), "r"(b1));
}

// ---------------------------------------------------------------------------
// 0) prep: zero agg+deg, split W = [Wl|Wr] into bf16 hi/lo
// ---------------------------------------------------------------------------
__global__ void prep_kernel(const float* __restrict__ Wl,
                            const float* __restrict__ Wr,
                            int n_agg4, int n_deg)
{
    int idx = blockIdx.x * blockDim.x + threadIdx.x;
    int stride = gridDim.x * blockDim.x;
    float4* a4 = reinterpret_cast<float4*>(g_agg);
    for (int i = idx; i < n_agg4; i += stride)
        a4[i] = make_float4(0.f, 0.f, 0.f, 0.f);
    for (int i = idx; i < n_deg; i += stride)
        g_deg[i] = 0.f;
    for (int i = idx; i < D * K2; i += stride) {
        int r = i / K2, k = i % K2;
        float w = (k < D) ? Wl[r * D + k] : Wr[r * D + (k - D)];
        __nv_bfloat16 h = __float2bfloat16(w);
        reinterpret_cast<__nv_bfloat16*>(g_Bhi4)[i] = h;
        reinterpret_cast<__nv_bfloat16*>(g_Blo4)[i] =
            __float2bfloat16(w - __bfloat162float(h));
    }
}

// ---------------------------------------------------------------------------
// 1) scatter: agg[dst] += x[src]; deg[dst] += 1   (red.global.add.v4.f32)
// ---------------------------------------------------------------------------
__global__ __launch_bounds__(192) void scatter_kernel(
    const float* __restrict__ x, const int* __restrict__ ei, int E)
{
    int e = blockIdx.x * 8 + threadIdx.y;
    if (e >= E) return;
    int c = threadIdx.x;                 // 0..23
    int src = __ldg(ei + e);
    int dst = __ldg(ei + E + e);

    float4 v = *reinterpret_cast<const float4*>(x + (size_t)src * D + c * 4);
    float* p = g_agg + (size_t)dst * D + c * 4;
    asm volatile("red.global.add.v4.f32 [%0], {%1,%2,%3,%4};"
                 :: "l"(p), "f"(v.x), "f"(v.y), "f"(v.z), "f"(v.w)
                 : "memory");
    if (c == 0) atomicAdd(g_deg + dst, 1.0f);
}

// ---------------------------------------------------------------------------
// 2) invert degree
// ---------------------------------------------------------------------------
__global__ void recip_kernel(int n) {
    int i = blockIdx.x * blockDim.x + threadIdx.x;
    if (i < n) g_deg[i] = 1.0f / fmaxf(g_deg[i], 1.0f);
}

// ---------------------------------------------------------------------------
// 3) GEMM: out = relu([agg*invdeg | x] @ [Wl|Wr]^T + bl)
//    A fragments LDG'd directly from global, bf16 hi/lo split in registers,
//    explicit next-k-step raw prefetch. Bhi AND Blo both resident in smem
//    (73.7 KB dynamic, XOR-swizzled) -> single 12-step mainloop, no B swap,
//    A read once. CTA: 256 threads = 8 warps, 128 rows; warp tile 16x96.
//    Per k-step: 24 MMA (Ahi,Alo x Bhi) then 12 MMA (Ahi x Blo), B-frag
//    registers reused between the two halves.
// ---------------------------------------------------------------------------
#define BRS 384                      // B row stride bytes (192 bf16)
#define SM_BLO_OFF (96 * BRS)
#define SM_TOTAL (2 * 96 * BRS)      // 73728 B

// swizzled 16B-chunk offset within a row
__device__ __forceinline__ int bswz(int row, int chunk) {
    return ((chunk & ~7) | ((chunk ^ row) & 7)) << 4;
}

__global__ __launch_bounds__(256, 2) void fused_gemm_kernel(
    const float* __restrict__ x, const float* __restrict__ bl,
    float* __restrict__ out, int N)
{
    extern __shared__ char smem[];

    const int tid  = threadIdx.x;
    const int wid  = tid >> 5;           // 0..7
    const int lane = tid & 31;
    const int m0   = blockIdx.x * 128;
    const int mbase = m0 + wid * 16;

    // --- stage Bhi + Blo (swizzled) ---
    for (int l = tid; l < 2304; l += 256) {
        int n = l / 24, q = l % 24;
        int so = n * BRS + bswz(n, q);
        *reinterpret_cast<uint4*>(smem + so) = g_Bhi4[l];
        *reinterpret_cast<uint4*>(smem + SM_BLO_OFF + so) = g_Blo4[l];
    }

    // per-lane A addressing (m16n8k16 fragment map)
    const int g = lane >> 2, t = lane & 3;
    const int r0 = mbase + g, r1 = r0 + 8;
    const bool ok0 = r0 < N, ok1 = r1 < N;
    const float inv0 = ok0 ? __ldg(g_deg + r0) : 1.f;
    const float inv1 = ok1 ? __ldg(g_deg + r1) : 1.f;
    const float* aggp0 = g_agg + (size_t)(ok0 ? r0 : 0) * D;
    const float* aggp1 = g_agg + (size_t)(ok1 ? r1 : 0) * D;
    const float* xp0   = x     + (size_t)(ok0 ? r0 : 0) * D;
    const float* xp1   = x     + (size_t)(ok1 ? r1 : 0) * D;

    // per-lane B ldmatrix addressing
    const int lrow8  = lane & 7;
    const int brow   = lrow8 + ((lane >> 4) << 3);
    const int bksel  = (lane >> 3) & 1;
    const uint32_t sb = smem_u32(smem);

    float acc[12][4];
#pragma unroll
    for (int j = 0; j < 12; ++j)
#pragma unroll
        for (int r = 0; r < 4; ++r) acc[j][r] = 0.f;

    // raw A loader for k-step ks: v[0]=row0/k, v[1]=row0/k+8, v[2]=row1/k, v[3]=row1/k+8
    auto load_raw = [&](int ks, float2* v) {
        const float2 z = make_float2(0.f, 0.f);
        const int col = (ks < 6) ? ks * 16 + 2 * t : (ks - 6) * 16 + 2 * t;
        const float* p0 = (ks < 6) ? aggp0 : xp0;
        const float* p1 = (ks < 6) ? aggp1 : xp1;
        v[0] = ok0 ? __ldg(reinterpret_cast<const float2*>(p0 + col))     : z;
        v[1] = ok0 ? __ldg(reinterpret_cast<const float2*>(p0 + col + 8)) : z;
        v[2] = ok1 ? __ldg(reinterpret_cast<const float2*>(p1 + col))     : z;
        v[3] = ok1 ? __ldg(reinterpret_cast<const float2*>(p1 + col + 8)) : z;
    };

    __syncthreads();

    float2 raw[4];
    load_raw(0, raw);

#pragma unroll
    for (int ks = 0; ks < 12; ++ks) {
        // prefetch next k-step's raw A
        float2 nxt[4];
        if (ks < 11) load_raw(ks + 1, nxt);

        // scale + bf16 hi/lo split
        const float sA = (ks < 6) ? inv0 : 1.f;
        const float sB = (ks < 6) ? inv1 : 1.f;
        float vx[4][2] = {{raw[0].x * sA, raw[0].y * sA},
                          {raw[2].x * sB, raw[2].y * sB},
                          {raw[1].x * sA, raw[1].y * sA},
                          {raw[3].x * sB, raw[3].y * sB}};
        uint32_t ahi[4], alo[4];
#pragma unroll
        for (int i = 0; i < 4; ++i) {
            ahi[i] = pack_bf16x2(vx[i][0], vx[i][1]);
            alo[i] = pack_bf16x2(vx[i][0] - __uint_as_float(ahi[i] << 16),
                                 vx[i][1] - __uint_as_float(ahi[i] & 0xffff0000u));
        }

        const int ch = 2 * ks + bksel;
        const uint32_t bOff = brow * BRS + bswz(lrow8, ch);

        // --- Bhi half: hi*Bhi + lo*Bhi ---
        uint32_t b[6][4];
#pragma unroll
        for (int q = 0; q < 6; ++q)
            LDSM_X4(b[q], sb + bOff + q * 16 * BRS);
#pragma unroll
        for (int j = 0; j < 12; ++j)
            mma_bf16(acc[j], ahi, b[j >> 1][(j & 1) * 2], b[j >> 1][(j & 1) * 2 + 1]);
#pragma unroll
        for (int j = 0; j < 12; ++j)
            mma_bf16(acc[j], alo, b[j >> 1][(j & 1) * 2], b[j >> 1][(j & 1) * 2 + 1]);

        // --- Blo half: hi*Blo (reuse b registers) ---
#pragma unroll
        for (int q = 0; q < 6; ++q)
            LDSM_X4(b[q], sb + SM_BLO_OFF + bOff + q * 16 * BRS);
#pragma unroll
        for (int j = 0; j < 12; ++j)
            mma_bf16(acc[j], ahi, b[j >> 1][(j & 1) * 2], b[j >> 1][(j & 1) * 2 + 1]);

#pragma unroll
        for (int i = 0; i < 4; ++i) raw[i] = nxt[i];
    }

    // --- epilogue: bias + relu + float2 stores ---
    const int erow = lane >> 2;
    const int ecol = (lane & 3) * 2;
#pragma unroll
    for (int j = 0; j < 12; ++j) {
        int col = j * 8 + ecol;
        float b0 = __ldg(bl + col);
        float b1 = __ldg(bl + col + 1);
        int row0 = mbase + erow;
        if (row0 < N) {
            float2 o = make_float2(fmaxf(acc[j][0] + b0, 0.f),
                                   fmaxf(acc[j][1] + b1, 0.f));
            *reinterpret_cast<float2*>(out + (size_t)row0 * D + col) = o;
        }
        int row1 = row0 + 8;
        if (row1 < N) {
            float2 o = make_float2(fmaxf(acc[j][2] + b0, 0.f),
                                   fmaxf(acc[j][3] + b1, 0.f));
            *reinterpret_cast<float2*>(out + (size_t)row1 * D + col) = o;
        }
    }
}

// ---------------------------------------------------------------------------
// kernel_launch
// ---------------------------------------------------------------------------
extern "C" void kernel_launch(void* const* d_in, const int* in_sizes, int n_in,
                              void* d_out, int out_size)
{
    const float* x  = (const float*)d_in[0];
    const int*   ei = (const int*)  d_in[1];
    const float* Wl = (const float*)d_in[2];
    const float* bl = (const float*)d_in[3];
    const float* Wr = (const float*)d_in[4];
    float* out = (float*)d_out;

    const int N = in_sizes[0] / D;
    const int E = in_sizes[1] / 2;

    cudaFuncSetAttribute(fused_gemm_kernel,
                         cudaFuncAttributeMaxDynamicSharedMemorySize, SM_TOTAL);

    prep_kernel<<<2048, 256>>>(Wl, Wr, (N * D) / 4, N);

    dim3 sblk(24, 8);
    scatter_kernel<<<(E + 7) / 8, sblk>>>(x, ei, E);

    recip_kernel<<<(N + 255) / 256, 256>>>(N);

    fused_gemm_kernel<<<(N + 127) / 128, 256, SM_TOTAL>>>(x, bl, out, N);
}